// round 4
// baseline (speedup 1.0000x reference)
#include <cuda_runtime.h>
#include <cuda_bf16.h>
#include <cstdint>

#define Bn   16384
#define INn  512
#define Hn   1024
#define OUTn 512
#define Mn   8
#define Rn   256
#define CYC  4

// ---------------- scratch (static device globals; no runtime allocation) ----
__device__ float g_h   [(size_t)Bn * Hn];        // 64 MB
__device__ float g_h2  [(size_t)Bn * Hn];        // 64 MB
__device__ float g_r   [(size_t)Bn * Hn];        // 64 MB (router features, 4*256)
__device__ float g_probs[(size_t)Bn * CYC * Mn]; // 2 MB
__device__ float g_wr1c[(size_t)Hn * Hn];        // 4 MB (diag(cycle_proj_c) @ Wr1, 4 blocks of 256 cols)

// ---------------- helpers ---------------------------------------------------
__device__ __forceinline__ void bsplit(float x, __nv_bfloat16& h, __nv_bfloat16& l) {
    h = __float2bfloat16(x);
    l = __float2bfloat16(x - __bfloat162float(h));
}

__device__ __forceinline__ void mma_bf16(float* c, const uint32_t* a, const uint32_t* b) {
    asm volatile(
        "mma.sync.aligned.m16n8k16.row.col.f32.bf16.bf16.f32 "
        "{%0,%1,%2,%3}, {%4,%5,%6,%7}, {%8,%9}, {%0,%1,%2,%3};\n"
        : "+f"(c[0]), "+f"(c[1]), "+f"(c[2]), "+f"(c[3])
        : "r"(a[0]), "r"(a[1]), "r"(a[2]), "r"(a[3]), "r"(b[0]), "r"(b[1]));
}

// A tile: 128 rows x 32 k, fp32 gmem -> hi/lo bf16 smem [row][k] (stride 40)
__device__ __forceinline__ void loadA(__nv_bfloat16 (*sAh)[40], __nv_bfloat16 (*sAl)[40],
                                      const float* __restrict__ A, int lda, int tid) {
    int r0 = tid >> 3;            // 0..31
    int kc = (tid & 7) << 2;      // 0,4,...,28
#pragma unroll
    for (int p = 0; p < 4; p++) {
        int r = p * 32 + r0;
        float4 v = *reinterpret_cast<const float4*>(A + (size_t)r * lda + kc);
        __nv_bfloat16 h0, h1, h2, h3, l0, l1, l2, l3;
        bsplit(v.x, h0, l0); bsplit(v.y, h1, l1);
        bsplit(v.z, h2, l2); bsplit(v.w, h3, l3);
        *reinterpret_cast<__nv_bfloat162*>(&sAh[r][kc])     = __halves2bfloat162(h0, h1);
        *reinterpret_cast<__nv_bfloat162*>(&sAh[r][kc + 2]) = __halves2bfloat162(h2, h3);
        *reinterpret_cast<__nv_bfloat162*>(&sAl[r][kc])     = __halves2bfloat162(l0, l1);
        *reinterpret_cast<__nv_bfloat162*>(&sAl[r][kc + 2]) = __halves2bfloat162(l2, l3);
    }
}

// B tile: 32 k x 128 n (row-major gmem) -> TRANSPOSED hi/lo bf16 smem [n][k] (stride 40)
__device__ __forceinline__ void loadB(__nv_bfloat16 (*sBh)[40], __nv_bfloat16 (*sBl)[40],
                                      const float* __restrict__ Wt, int ldb, int tid) {
    int n  = tid & 127;
    int kb = (tid >> 7) << 2;     // 0 or 4
#pragma unroll
    for (int p = 0; p < 4; p++) {
        int k = p * 8 + kb;       // covers all 32 k rows
        float x0 = Wt[(size_t)(k + 0) * ldb + n];
        float x1 = Wt[(size_t)(k + 1) * ldb + n];
        float x2 = Wt[(size_t)(k + 2) * ldb + n];
        float x3 = Wt[(size_t)(k + 3) * ldb + n];
        __nv_bfloat16 h0, h1, h2, h3, l0, l1, l2, l3;
        bsplit(x0, h0, l0); bsplit(x1, h1, l1);
        bsplit(x2, h2, l2); bsplit(x3, h3, l3);
        *reinterpret_cast<__nv_bfloat162*>(&sBh[n][k])     = __halves2bfloat162(h0, h1);
        *reinterpret_cast<__nv_bfloat162*>(&sBh[n][k + 2]) = __halves2bfloat162(h2, h3);
        *reinterpret_cast<__nv_bfloat162*>(&sBl[n][k])     = __halves2bfloat162(l0, l1);
        *reinterpret_cast<__nv_bfloat162*>(&sBl[n][k + 2]) = __halves2bfloat162(l2, l3);
    }
}

// one k16 step: 4 m-tiles x 4 n-tiles, bf16x3 (Ah*Bh + Ah*Bl + Al*Bh)
__device__ __forceinline__ void mma_step(float c[4][4][4],
                                         __nv_bfloat16 (*sAh)[40], __nv_bfloat16 (*sAl)[40],
                                         __nv_bfloat16 (*sBh)[40], __nv_bfloat16 (*sBl)[40],
                                         int kk, int wm, int wn, int lane) {
    int qr  = lane >> 2;
    int qc2 = (lane & 3) << 1;
    uint32_t ah[4][4], al[4][4];
#pragma unroll
    for (int im = 0; im < 4; im++) {
        int rb = wm + im * 16 + qr;
        ah[im][0] = *reinterpret_cast<const uint32_t*>(&sAh[rb][kk + qc2]);
        ah[im][1] = *reinterpret_cast<const uint32_t*>(&sAh[rb + 8][kk + qc2]);
        ah[im][2] = *reinterpret_cast<const uint32_t*>(&sAh[rb][kk + qc2 + 8]);
        ah[im][3] = *reinterpret_cast<const uint32_t*>(&sAh[rb + 8][kk + qc2 + 8]);
        al[im][0] = *reinterpret_cast<const uint32_t*>(&sAl[rb][kk + qc2]);
        al[im][1] = *reinterpret_cast<const uint32_t*>(&sAl[rb + 8][kk + qc2]);
        al[im][2] = *reinterpret_cast<const uint32_t*>(&sAl[rb][kk + qc2 + 8]);
        al[im][3] = *reinterpret_cast<const uint32_t*>(&sAl[rb + 8][kk + qc2 + 8]);
    }
#pragma unroll
    for (int in = 0; in < 4; in++) {
        int cb = wn + in * 8 + qr;
        uint32_t bh[2], bl[2];
        bh[0] = *reinterpret_cast<const uint32_t*>(&sBh[cb][kk + qc2]);
        bh[1] = *reinterpret_cast<const uint32_t*>(&sBh[cb][kk + qc2 + 8]);
        bl[0] = *reinterpret_cast<const uint32_t*>(&sBl[cb][kk + qc2]);
        bl[1] = *reinterpret_cast<const uint32_t*>(&sBl[cb][kk + qc2 + 8]);
#pragma unroll
        for (int im = 0; im < 4; im++) {
            mma_bf16(c[im][in], ah[im], bh);
            mma_bf16(c[im][in], ah[im], bl);
            mma_bf16(c[im][in], al[im], bh);
        }
    }
}

// ---------------- plain GEMM: C = A @ W + bias  (MODE 1: relu + bias idx n%256)
template <int MODE>
__global__ void __launch_bounds__(256) gemm_kernel(
    const float* __restrict__ A, int lda,
    const float* __restrict__ W, int ldb,
    const float* __restrict__ bias,
    float* __restrict__ C, int N, int K) {
    __shared__ __nv_bfloat16 sAh[128][40], sAl[128][40], sBh[128][40], sBl[128][40];
    int tid = threadIdx.x, lane = tid & 31, wid = tid >> 5;
    int wm = (wid & 1) * 64, wn = (wid >> 1) * 32;
    int bR = blockIdx.y * 128, bC = blockIdx.x * 128;

    float c[4][4][4];
#pragma unroll
    for (int i = 0; i < 4; i++)
#pragma unroll
        for (int j = 0; j < 4; j++)
#pragma unroll
            for (int q = 0; q < 4; q++) c[i][j][q] = 0.f;

    const float* Ap = A + (size_t)bR * lda;
    const float* Wp = W + bC;
    for (int kt = 0; kt < K; kt += 32) {
        loadA(sAh, sAl, Ap + kt, lda, tid);
        loadB(sBh, sBl, Wp + (size_t)kt * ldb, ldb, tid);
        __syncthreads();
        mma_step(c, sAh, sAl, sBh, sBl, 0,  wm, wn, lane);
        mma_step(c, sAh, sAl, sBh, sBl, 16, wm, wn, lane);
        __syncthreads();
    }

    int qr = lane >> 2, qc2 = (lane & 3) << 1;
#pragma unroll
    for (int im = 0; im < 4; im++) {
        int gr = bR + wm + im * 16 + qr;
#pragma unroll
        for (int in = 0; in < 4; in++) {
            int gc = bC + wn + in * 8 + qc2;
            float2 bv;
            if (MODE == 1) bv = *reinterpret_cast<const float2*>(&bias[gc & (Rn - 1)]);
            else           bv = *reinterpret_cast<const float2*>(&bias[gc]);
            float v0 = c[im][in][0] + bv.x;
            float v1 = c[im][in][1] + bv.y;
            float v2 = c[im][in][2] + bv.x;
            float v3 = c[im][in][3] + bv.y;
            if (MODE == 1) {
                v0 = fmaxf(v0, 0.f); v1 = fmaxf(v1, 0.f);
                v2 = fmaxf(v2, 0.f); v3 = fmaxf(v3, 0.f);
            }
            float2 r0 = {v0, v1}, r1 = {v2, v3};
            *reinterpret_cast<float2*>(&C[(size_t)gr * N + gc])       = r0;
            *reinterpret_cast<float2*>(&C[(size_t)(gr + 8) * N + gc]) = r1;
        }
    }
}

// ---------------- fused expert kernel ---------------------------------------
// dst[b,d] = sum_m probs[b,cyc,m] * relu( (src @ W_mod[m])[b,d] + b_mod[m,d] )
__global__ void __launch_bounds__(256) expert_kernel(
    const float* __restrict__ src, float* __restrict__ dst,
    const float* __restrict__ Wmod, const float* __restrict__ bmod,
    const float* __restrict__ probs, int cyc) {
    __shared__ __nv_bfloat16 sAh[128][40], sAl[128][40], sBh[128][40], sBl[128][40];
    int tid = threadIdx.x, lane = tid & 31, wid = tid >> 5;
    int wm = (wid & 1) * 64, wn = (wid >> 1) * 32;
    int bR = blockIdx.y * 128, bC = blockIdx.x * 128;
    int qr = lane >> 2, qc2 = (lane & 3) << 1;

    float o[4][4][4];
#pragma unroll
    for (int i = 0; i < 4; i++)
#pragma unroll
        for (int j = 0; j < 4; j++)
#pragma unroll
            for (int q = 0; q < 4; q++) o[i][j][q] = 0.f;

    const float* Ap = src + (size_t)bR * Hn;

    for (int m = 0; m < Mn; m++) {
        float c[4][4][4];
#pragma unroll
        for (int i = 0; i < 4; i++)
#pragma unroll
            for (int j = 0; j < 4; j++)
#pragma unroll
                for (int q = 0; q < 4; q++) c[i][j][q] = 0.f;

        const float* Wm = Wmod + (size_t)m * Hn * Hn + bC;
        for (int kt = 0; kt < Hn; kt += 32) {
            loadA(sAh, sAl, Ap + kt, Hn, tid);
            loadB(sBh, sBl, Wm + (size_t)kt * Hn, Hn, tid);
            __syncthreads();
            mma_step(c, sAh, sAl, sBh, sBl, 0,  wm, wn, lane);
            mma_step(c, sAh, sAl, sBh, sBl, 16, wm, wn, lane);
            __syncthreads();
        }

#pragma unroll
        for (int im = 0; im < 4; im++) {
            int gr = bR + wm + im * 16 + qr;
            float p0 = probs[((size_t)gr * CYC + cyc) * Mn + m];
            float p8 = probs[((size_t)(gr + 8) * CYC + cyc) * Mn + m];
#pragma unroll
            for (int in = 0; in < 4; in++) {
                int gc = bC + wn + in * 8 + qc2;
                float2 bv = *reinterpret_cast<const float2*>(&bmod[(size_t)m * Hn + gc]);
                o[im][in][0] += p0 * fmaxf(c[im][in][0] + bv.x, 0.f);
                o[im][in][1] += p0 * fmaxf(c[im][in][1] + bv.y, 0.f);
                o[im][in][2] += p8 * fmaxf(c[im][in][2] + bv.x, 0.f);
                o[im][in][3] += p8 * fmaxf(c[im][in][3] + bv.y, 0.f);
            }
        }
    }

#pragma unroll
    for (int im = 0; im < 4; im++) {
        int gr = bR + wm + im * 16 + qr;
#pragma unroll
        for (int in = 0; in < 4; in++) {
            int gc = bC + wn + in * 8 + qc2;
            float2 r0 = {o[im][in][0], o[im][in][1]};
            float2 r1 = {o[im][in][2], o[im][in][3]};
            *reinterpret_cast<float2*>(&dst[(size_t)gr * Hn + gc])       = r0;
            *reinterpret_cast<float2*>(&dst[(size_t)(gr + 8) * Hn + gc]) = r1;
        }
    }
}

// ---------------- router prep: Wr1c[k, c*256+j] = (c*Wc[k]+bc[k]) * Wr1[k,j] -
__global__ void prep_wr1c(const float* __restrict__ Wr1, const float* __restrict__ Wc,
                          const float* __restrict__ bc, float* __restrict__ out) {
    int k = blockIdx.x;       // 0..1023
    int j = threadIdx.x;      // 0..255
    float w   = Wr1[(size_t)k * Rn + j];
    float wck = Wc[k];
    float bck = bc[k];
#pragma unroll
    for (int c = 0; c < CYC; c++)
        out[(size_t)k * Hn + c * Rn + j] = ((float)c * wck + bck) * w;
}

// ---------------- probs: softmax(relu_feats @ Wr2 + br2) per (b, cycle) -----
__global__ void probs_kernel(const float* __restrict__ r, const float* __restrict__ Wr2,
                             const float* __restrict__ br2, float* __restrict__ probs) {
    int wid = threadIdx.x >> 5, lane = threadIdx.x & 31;
    int idx = blockIdx.x * 8 + wid;  // 0 .. Bn*CYC-1
    int b = idx >> 2, c = idx & 3;
    const float* rr = r + (size_t)b * Hn + c * Rn;

    float acc[8];
#pragma unroll
    for (int m = 0; m < 8; m++) acc[m] = 0.f;
    for (int k = lane; k < Rn; k += 32) {
        float rv = rr[k];
        float4 w0 = *reinterpret_cast<const float4*>(&Wr2[(size_t)k * 8]);
        float4 w1 = *reinterpret_cast<const float4*>(&Wr2[(size_t)k * 8 + 4]);
        acc[0] += rv * w0.x; acc[1] += rv * w0.y; acc[2] += rv * w0.z; acc[3] += rv * w0.w;
        acc[4] += rv * w1.x; acc[5] += rv * w1.y; acc[6] += rv * w1.z; acc[7] += rv * w1.w;
    }
#pragma unroll
    for (int off = 16; off > 0; off >>= 1)
#pragma unroll
        for (int m = 0; m < 8; m++) acc[m] += __shfl_xor_sync(0xffffffffu, acc[m], off);

    float mx = -1e30f;
#pragma unroll
    for (int m = 0; m < 8; m++) { acc[m] += br2[m]; mx = fmaxf(mx, acc[m]); }
    float s = 0.f;
#pragma unroll
    for (int m = 0; m < 8; m++) { acc[m] = expf(acc[m] - mx); s += acc[m]; }
    float inv = 1.f / s;
    if (lane < 8) probs[(size_t)idx * 8 + lane] = acc[lane] * inv;
}

// ---------------- launch -----------------------------------------------------
extern "C" void kernel_launch(void* const* d_in, const int* in_sizes, int n_in,
                              void* d_out, int out_size) {
    (void)in_sizes; (void)n_in; (void)out_size;
    const float* x     = (const float*)d_in[0];
    const float* W_in  = (const float*)d_in[1];
    const float* b_in  = (const float*)d_in[2];
    const float* W_mod = (const float*)d_in[3];
    const float* b_mod = (const float*)d_in[4];
    const float* Wr1   = (const float*)d_in[5];
    const float* br1   = (const float*)d_in[6];
    const float* Wr2   = (const float*)d_in[7];
    const float* br2   = (const float*)d_in[8];
    const float* Wc    = (const float*)d_in[9];
    const float* bc    = (const float*)d_in[10];
    const float* W_out = (const float*)d_in[11];
    const float* b_out = (const float*)d_in[12];
    float* out = (float*)d_out;

    float *h, *h2, *r, *probs, *wr1c;
    cudaGetSymbolAddress((void**)&h,     g_h);
    cudaGetSymbolAddress((void**)&h2,    g_h2);
    cudaGetSymbolAddress((void**)&r,     g_r);
    cudaGetSymbolAddress((void**)&probs, g_probs);
    cudaGetSymbolAddress((void**)&wr1c,  g_wr1c);

    dim3 blk(256);
    dim3 gH(Hn / 128, Bn / 128);     // N=1024 tiles
    dim3 gO(OUTn / 128, Bn / 128);   // N=512 tiles

    // 1. fold cycle projection into router weights (all 4 cycles)
    prep_wr1c<<<Hn, 256>>>(Wr1, Wc, bc, wr1c);
    // 2. h = x @ W_in + b_in   (h also serves as "orig")
    gemm_kernel<0><<<gH, blk>>>(x, INn, W_in, Hn, b_in, h, Hn, INn);
    // 3. router features for all 4 cycles: relu(orig @ Wr1c + br1)
    gemm_kernel<1><<<gH, blk>>>(h, Hn, wr1c, Hn, br1, r, Hn, Hn);
    // 4. probs[b, c, m] = softmax(feats @ Wr2 + br2)
    probs_kernel<<<(Bn * CYC) / 8, 256>>>(r, Wr2, br2, probs);
    // 5. four expert/mixture cycles (max_cycles is fixed at 4 by the dataset)
    expert_kernel<<<gH, blk>>>(h,  h2, W_mod, b_mod, probs, 0);
    expert_kernel<<<gH, blk>>>(h2, h,  W_mod, b_mod, probs, 1);
    expert_kernel<<<gH, blk>>>(h,  h2, W_mod, b_mod, probs, 2);
    expert_kernel<<<gH, blk>>>(h2, h,  W_mod, b_mod, probs, 3);
    // 6. out = h @ W_out + b_out
    gemm_kernel<0><<<gO, blk>>>(h, Hn, W_out, OUTn, b_out, out, OUTn, Hn);
}